// round 17
// baseline (speedup 1.0000x reference)
#include <cuda_runtime.h>
#include <cstdint>
#include <cstddef>

#define TT   2048
#define BB   64
#define NIN  128
#define HH   256
#define NOUT 128
#define MROWS (TT * BB)   // 131072

__device__ __align__(16) float g_xp[(size_t)TT * BB * HH];  // 128 MB

__device__ __forceinline__ unsigned long long fma2(unsigned long long a,
                                                   unsigned long long b,
                                                   unsigned long long c) {
    unsigned long long d;
    asm("fma.rn.f32x2 %0, %1, %2, %3;" : "=l"(d) : "l"(a), "l"(b), "l"(c));
    return d;
}
__device__ __forceinline__ float red2(unsigned long long a) {
    float lo, hi;
    asm("mov.b64 {%0, %1}, %2;" : "=f"(lo), "=f"(hi) : "l"(a));
    return lo + hi;
}
__device__ __forceinline__ uint32_t smem_u32(const void* p) {
    uint32_t a;
    asm("{ .reg .u64 t; cvta.to.shared.u64 t, %1; cvt.u32.u64 %0, t; }" : "=r"(a) : "l"(p));
    return a;
}
__device__ __forceinline__ uint32_t mapa_u32(uint32_t addr, uint32_t rank) {
    uint32_t r;
    asm("mapa.shared::cluster.u32 %0, %1, %2;" : "=r"(r) : "r"(addr), "r"(rank));
    return r;
}
__device__ __forceinline__ void cluster_sync_() {
    asm volatile("barrier.cluster.arrive.aligned;" ::: "memory");
    asm volatile("barrier.cluster.wait.aligned;" ::: "memory");
}
__device__ __forceinline__ void nbar_sync(int id, int cnt) {
    asm volatile("bar.sync %0, %1;" :: "r"(id), "r"(cnt) : "memory");
}
__device__ __forceinline__ void nbar_arrive(int id, int cnt) {
    asm volatile("bar.arrive %0, %1;" :: "r"(id), "r"(cnt) : "memory");
}
// ---- tagged-slot DSMEM exchange (plain path; measured ≡ mbarrier path) ----
__device__ __forceinline__ void st_slot(uint32_t addr, float h, uint32_t tag) {
    unsigned long long v;
    asm("mov.b64 %0, {%1, %2};" : "=l"(v) : "r"(__float_as_uint(h)), "r"(tag));
    asm volatile("st.relaxed.cluster.shared::cluster.b64 [%0], %1;"
                 :: "r"(addr), "l"(v) : "memory");
}
__device__ __forceinline__ float poll_slot(uint32_t addr, uint32_t exp) {
    unsigned long long v;
    uint32_t lo, hi;
    do {
        asm volatile("ld.relaxed.cluster.shared::cta.b64 %0, [%1];"
                     : "=l"(v) : "r"(addr) : "memory");
        asm("mov.b64 {%0, %1}, %2;" : "=r"(lo), "=r"(hi) : "l"(v));
    } while (hi != exp);
    return __uint_as_float(lo);
}
// tanh(x) = 1 - 2/(exp(2x)+1), MUFU-based (~45 cyc)
__device__ __forceinline__ float fast_tanh(float x) {
    float e, r;
    float t = x * 2.8853900817779268f;      // 2*log2(e)
    asm("ex2.approx.f32 %0, %1;" : "=f"(e) : "f"(t));
    float d = e + 1.0f;
    asm("rcp.approx.f32 %0, %1;" : "=f"(r) : "f"(d));
    return fmaf(-2.0f, r, 1.0f);
}

// dummy pad kernel — keeps k_scan at the profiled launch index (3)
__global__ void k_nop() {}

// =====================================================================
// K1 projection (R8 version — measured best)
// =====================================================================
template<int O, int K, bool TWOB>
__global__ void __launch_bounds__(512, 1)
k_proj(const float* __restrict__ A, const float* __restrict__ W,
       const float* __restrict__ bias1, const float* __restrict__ bias2,
       float* __restrict__ C) {
    constexpr int G   = 512 / O;
    constexpr int KT  = K / G;
    constexpr int KT4 = KT / 4;
    constexpr int RPB = 64;
    constexpr int RG  = 8;
    constexpr int NGR = RPB / RG;
    constexpr int NLD = RG * K / 4;

    __shared__ __align__(16) float stage[2][RG * K];
    __shared__ float scr[2][G - 1][RG][O];

    const int tid = threadIdx.x;
    const int o = tid % O;
    const int g = tid / O;
    const size_t m0 = (size_t)blockIdx.x * RPB;

    ulonglong2 w[KT4];
    {
        const ulonglong2* wr = (const ulonglong2*)(W + (size_t)o * K + g * KT);
#pragma unroll
        for (int i = 0; i < KT4; i++) w[i] = wr[i];
    }
    const float bias = TWOB ? (bias1[o] + bias2[o]) : bias1[o];

    float4 ld = make_float4(0.f, 0.f, 0.f, 0.f);
    if (tid < NLD) ld = __ldg(((const float4*)(A + m0 * K)) + tid);

    for (int grp = 0; grp < NGR; grp++) {
        const int buf = grp & 1;
        if (tid < NLD) ((float4*)stage[buf])[tid] = ld;
        __syncthreads();
        if (grp + 1 < NGR && tid < NLD)
            ld = __ldg(((const float4*)(A + (m0 + (size_t)(grp + 1) * RG) * K)) + tid);

        float pr[RG];
#pragma unroll
        for (int r = 0; r < RG; r++) {
            const ulonglong2* xr = (const ulonglong2*)(stage[buf] + r * K + g * KT);
            unsigned long long a0 = 0ull, a1 = 0ull;
#pragma unroll
            for (int i = 0; i < KT4; i++) {
                ulonglong2 v = xr[i];
                a0 = fma2(w[i].x, v.x, a0);
                a1 = fma2(w[i].y, v.y, a1);
            }
            pr[r] = red2(a0) + red2(a1);
        }
        if (g) {
#pragma unroll
            for (int r = 0; r < RG; r++) scr[buf][g - 1][r][o] = pr[r];
        }
        __syncthreads();
        if (!g) {
#pragma unroll
            for (int r = 0; r < RG; r++) {
                float s = pr[r] + bias;
#pragma unroll
                for (int q = 0; q < G - 1; q++) s += scr[buf][q][r][o];
                C[(m0 + (size_t)grp * RG + r) * O + o] = s;
            }
        }
    }
}

// =====================================================================
// K2: recurrent scan + FUSED output projection.
// Cluster of 2 CTAs per batch (128 CTAs). 320 threads:
//   g0 (tid<128):   local k-half FMA -> scr0            (off chain)
//   g1 (128..255):  peer recv + FMA + FINALIZE + send   (the chain)
//                   also writes h into hring[4] history
//   wk (256..319):  y(t-2) = w_out[o] . hring[(t-2)&3] + b_out[o]
//                   (w_out k<128 in regs; k>=128 in smem, 132-stride)
// Barriers: 1 = step pace (g1 arrives; g0+wk sync; count 320)
//           2 = scr0 ready (g0 arrives; g1 syncs; count 256)
//           3 = g1-only compact fence (count 128)
// =====================================================================
#define WLD 132   // w_out smem row stride (132 % 32 = 4 -> optimal LDS.128)

__global__ void __cluster_dims__(2, 1, 1) __launch_bounds__(320, 1)
k_scan(const float* __restrict__ w_hh, const float* __restrict__ w_out,
       const float* __restrict__ b_out, float* __restrict__ out) {
    __shared__ __align__(16) float hbuf[2][HH];
    __shared__ float scr0[2][128];
    __shared__ __align__(16) unsigned long long pbuf[2][128];
    __shared__ __align__(16) float hring[4][HH];
    __shared__ __align__(16) float wout_s[64 * WLD];

    const int tid = threadIdx.x;
    const int jj = tid & 127;
    const int rank = blockIdx.x & 1;
    const int b = blockIdx.x >> 1;
    const int j = rank * 128 + jj;
    const int peerbase = (rank ^ 1) * 128;

    // ---- role-specific register state ----
    ulonglong2 w[32];          // g0/g1: w_hh chunk; wk: w_out k<128
    float bias = 0.f;
    int o = 0, wkw = 0;
    if (tid < 256) {
        const int kbase = (tid < 128) ? rank * 128 : peerbase;
        const ulonglong2* wr = (const ulonglong2*)(w_hh + (size_t)j * HH + kbase);
#pragma unroll
        for (int i = 0; i < 32; i++) w[i] = wr[i];
    } else {
        wkw = tid - 256;                       // 0..63
        o = rank * 64 + wkw;
        const ulonglong2* wr = (const ulonglong2*)(w_out + (size_t)o * HH);
#pragma unroll
        for (int i = 0; i < 32; i++) w[i] = wr[i];   // k in [0,128)
        bias = b_out[o];
    }

    // init smem
    for (int i = tid; i < 2 * HH; i += 320) ((float*)hbuf)[i] = 0.0f;
    for (int i = tid; i < 2 * 128; i += 320) ((unsigned long long*)pbuf)[i] = 0ull;
    for (int idx = tid; idx < 64 * 128; idx += 320) {
        int r = idx >> 7, c = idx & 127;       // w_out k in [128,256)
        wout_s[r * WLD + c] = w_out[(size_t)(rank * 64 + r) * HH + 128 + c];
    }
    __syncthreads();
    cluster_sync_();   // peer slots zeroed before any remote store

    const uint32_t peer = rank ^ 1;
    const uint32_t rem_pb0 = mapa_u32(smem_u32(&pbuf[0][jj]), peer);
    const uint32_t rem_pb1 = mapa_u32(smem_u32(&pbuf[1][jj]), peer);
    const uint32_t loc_pb0 = smem_u32(&pbuf[0][jj]);
    const uint32_t loc_pb1 = smem_u32(&pbuf[1][jj]);

    const size_t STRIDE = (size_t)BB * HH;
    const float* xp_ptr = g_xp + (size_t)b * HH + j;

    // 4-deep xp prefetch ring — g1 (finisher) only
    float x0 = 0.f, x1 = 0.f, x2 = 0.f, x3 = 0.f;
    if (tid >= 128 && tid < 256) {
        x0 = __ldg(xp_ptr);
        x1 = __ldg(xp_ptr + STRIDE);
        x2 = __ldg(xp_ptr + 2 * STRIDE);
        x3 = __ldg(xp_ptr + 3 * STRIDE);
        xp_ptr += 4 * STRIDE;
    }

    for (int tt = 0; tt < TT; tt++) {
        const int p = tt & 1;
        const int rp = p ^ 1;

        if (tid < 128) {
            // ---- g0: local-half producer ----
            if (tt) nbar_sync(1, 320);
            const ulonglong2* hr = (const ulonglong2*)(&hbuf[rp][rank * 128]);
            unsigned long long a0 = 0ull, a1 = 0ull, a2 = 0ull, a3 = 0ull;
#pragma unroll
            for (int i = 0; i < 32; i += 2) {
                ulonglong2 v0 = hr[i];
                ulonglong2 v1 = hr[i + 1];
                a0 = fma2(w[i].x, v0.x, a0);
                a1 = fma2(w[i].y, v0.y, a1);
                a2 = fma2(w[i + 1].x, v1.x, a2);
                a3 = fma2(w[i + 1].y, v1.y, a3);
            }
            scr0[p][jj] = (red2(a0) + red2(a1)) + (red2(a2) + red2(a3));
            nbar_arrive(2, 256);
        } else if (tid < 256) {
            // ---- g1: peer-half consumer + FINISHER (the chain) ----
            float xp_use = x0;
            x0 = x1; x1 = x2; x2 = x3;
            x3 = (tt + 4 < TT) ? __ldg(xp_ptr) : 0.f;
            xp_ptr += STRIDE;

            float h_own = poll_slot(rp ? loc_pb1 : loc_pb0, (uint32_t)tt);
            hbuf[rp][peerbase + jj] = h_own;            // compact for FMA
            hring[(tt - 1) & 3][peerbase + jj] = h_own; // history (peer half)
            nbar_sync(3, 128);

            const ulonglong2* hr = (const ulonglong2*)(&hbuf[rp][peerbase]);
            unsigned long long a0 = 0ull, a1 = 0ull, a2 = 0ull, a3 = 0ull;
#pragma unroll
            for (int i = 0; i < 32; i += 2) {
                ulonglong2 v0 = hr[i];
                ulonglong2 v1 = hr[i + 1];
                a0 = fma2(w[i].x, v0.x, a0);
                a1 = fma2(w[i].y, v0.y, a1);
                a2 = fma2(w[i + 1].x, v1.x, a2);
                a3 = fma2(w[i + 1].y, v1.y, a3);
            }
            float part = (red2(a0) + red2(a1)) + (red2(a2) + red2(a3));

            nbar_sync(2, 256);          // g0 arrived long ago
            float h = fast_tanh(part + scr0[p][jj] + xp_use);
            st_slot(p ? rem_pb1 : rem_pb0, h, (uint32_t)(tt + 1));  // send
            hbuf[p][j] = h;             // local copy for g0
            hring[tt & 3][j] = h;       // history (own half)
            nbar_arrive(1, 320);        // release g0 + wk into step t+1
        } else {
            // ---- wk: trailing output projection y(tt-2) ----
            if (tt) nbar_sync(1, 320);
            if (tt >= 2) {
                const int t = tt - 2;
                const ulonglong2* hs2 = (const ulonglong2*)(&hring[t & 3][0]);
                unsigned long long a0 = 0ull, a1 = 0ull, a2 = 0ull, a3 = 0ull;
#pragma unroll
                for (int i = 0; i < 32; i += 2) {   // k in [0,128): reg weights
                    ulonglong2 v0 = hs2[i];
                    ulonglong2 v1 = hs2[i + 1];
                    a0 = fma2(w[i].x, v0.x, a0);
                    a1 = fma2(w[i].y, v0.y, a1);
                    a2 = fma2(w[i + 1].x, v1.x, a2);
                    a3 = fma2(w[i + 1].y, v1.y, a3);
                }
                const ulonglong2* ws2 = (const ulonglong2*)(wout_s + wkw * WLD);
#pragma unroll
                for (int i = 0; i < 32; i += 2) {   // k in [128,256): smem
                    ulonglong2 v0 = hs2[32 + i];
                    ulonglong2 v1 = hs2[33 + i];
                    ulonglong2 w0 = ws2[i];
                    ulonglong2 w1 = ws2[i + 1];
                    a0 = fma2(w0.x, v0.x, a0);
                    a1 = fma2(w0.y, v0.y, a1);
                    a2 = fma2(w1.x, v1.x, a2);
                    a3 = fma2(w1.y, v1.y, a3);
                }
                float y = (red2(a0) + red2(a1)) + (red2(a2) + red2(a3)) + bias;
                out[((size_t)t * BB + b) * NOUT + o] = y;
            }
        }
    }

    // ---- tail: finish y(TT-2), y(TT-1) ----
    if (tid >= 128 && tid < 256) {
        // receive peer half of h(TT-1) (sent with tag TT into slot 1)
        float hlast = poll_slot(loc_pb1, (uint32_t)TT);
        hring[(TT - 1) & 3][peerbase + jj] = hlast;
    }
    __syncthreads();
    if (tid >= 256) {
#pragma unroll
        for (int t = TT - 2; t < TT; t++) {
            const ulonglong2* hs2 = (const ulonglong2*)(&hring[t & 3][0]);
            unsigned long long a0 = 0ull, a1 = 0ull, a2 = 0ull, a3 = 0ull;
#pragma unroll
            for (int i = 0; i < 32; i += 2) {
                ulonglong2 v0 = hs2[i];
                ulonglong2 v1 = hs2[i + 1];
                a0 = fma2(w[i].x, v0.x, a0);
                a1 = fma2(w[i].y, v0.y, a1);
                a2 = fma2(w[i + 1].x, v1.x, a2);
                a3 = fma2(w[i + 1].y, v1.y, a3);
            }
            const ulonglong2* ws2 = (const ulonglong2*)(wout_s + wkw * WLD);
#pragma unroll
            for (int i = 0; i < 32; i += 2) {
                ulonglong2 v0 = hs2[32 + i];
                ulonglong2 v1 = hs2[33 + i];
                ulonglong2 w0 = ws2[i];
                ulonglong2 w1 = ws2[i + 1];
                a0 = fma2(w0.x, v0.x, a0);
                a1 = fma2(w0.y, v0.y, a1);
                a2 = fma2(w1.x, v1.x, a2);
                a3 = fma2(w1.y, v1.y, a3);
            }
            float y = (red2(a0) + red2(a1)) + (red2(a2) + red2(a3)) + bias;
            out[((size_t)t * BB + b) * NOUT + o] = y;
        }
    }
    cluster_sync_();
}

// =====================================================================
// Launch sequence: k1(0), nop(1), nop(2), scan(3) — k3 fused into scan.
// =====================================================================
extern "C" void kernel_launch(void* const* d_in, const int* in_sizes, int n_in,
                              void* d_out, int out_size) {
    const float* x     = (const float*)d_in[0];
    const float* w_ih  = (const float*)d_in[1];
    const float* w_hh  = (const float*)d_in[2];
    const float* b_ih  = (const float*)d_in[3];
    const float* b_hh  = (const float*)d_in[4];
    const float* w_out = (const float*)d_in[5];
    const float* b_out = (const float*)d_in[6];
    float* out = (float*)d_out;

    float* xp;
    cudaGetSymbolAddress((void**)&xp, g_xp);

    k_proj<HH, NIN, true><<<MROWS / 64, 512>>>(x, w_ih, b_ih, b_hh, xp);
    k_nop<<<1, 32>>>();
    k_nop<<<1, 32>>>();
    k_scan<<<2 * BB, 320>>>(w_hh, w_out, b_out, out);
}